// round 11
// baseline (speedup 1.0000x reference)
#include <cuda_runtime.h>

// Dense_RBS_density_3D: rho_out = W rho W^T, W = 39 sparse Givens layers
// (38 disjoint 2x2 column rotations each) on the C(40,2)=780-dim basis.
// K(M) = (M W^T)^T = W M^T applied twice => W rho W^T. Two launches with a
// private __device__ scratch between.
//
// R11 vs R10 (same geometry: 30 rows/tile, 512 thr, 2 CTAs/SM, 93.7 KB):
// 4 rows interleaved per float4 smem lane (rows 0..27 = 7 quad-rows,
// LDS.128/STS.128, 8 f32x2 per item-gate covering 4 rotations; walk cost
// amortized 4x). Rows 28-29 stay on the proven u64 path (warp 7).
// NOTE: transposed quad store must be 2x STG.64 (r0=30t is 2 mod 4 for odd
// t -> STG.128 would be misaligned).

#define DD      780
#define NGATES  39
#define NBATCH  64
#define RROWS   30
#define NQR     7             // quad-rows (rows 0..27)
#define NTILES  26            // 780 / 30
#define STRIDEQ 781           // float4 stride per quad-row (odd)
#define THREADS 512
#define QITEMS  (NQR * DD)                      // 5460
#define QFULL   ((QITEMS / THREADS) * THREADS)  // 5120
#define QBYTES  (NQR * STRIDEQ * 16)            // 87,472

__device__ float g_tmp[(size_t)NBATCH * DD * DD];  // 155.7 MB scratch

typedef unsigned long long u64;

__device__ __forceinline__ u64 f2pack(float lo, float hi) {
    u64 r; asm("mov.b64 %0, {%1, %2};" : "=l"(r) : "f"(lo), "f"(hi)); return r;
}
__device__ __forceinline__ void f2unpack(float& lo, float& hi, u64 v) {
    asm("mov.b64 {%0, %1}, %2;" : "=f"(lo), "=f"(hi) : "l"(v));
}
__device__ __forceinline__ u64 f2mul(u64 a, u64 b) {
    u64 r; asm("mul.rn.f32x2 %0, %1, %2;" : "=l"(r) : "l"(a), "l"(b)); return r;
}
__device__ __forceinline__ u64 f2fma(u64 a, u64 b, u64 c) {
    u64 r; asm("fma.rn.f32x2 %0, %1, %2, %3;" : "=l"(r) : "l"(a), "l"(b), "l"(c));
    return r;
}

__device__ __forceinline__ void rbs_body(const float* __restrict__ in,
                                         float* __restrict__ out,
                                         const float* __restrict__ angles) {
    extern __shared__ char smem_raw[];
    float4* tileQ = (float4*)smem_raw;                 // [NQR][STRIDEQ]
    u64*    tileP = (u64*)(smem_raw + QBYTES);         // [DD] rows 28,29
    __shared__ float s_cos[NGATES], s_sin[NGATES];

    const int tid = threadIdx.x;
    const int b   = blockIdx.x / NTILES;
    const int t   = blockIdx.x - b * NTILES;
    const int r0  = t * RROWS;

    if (tid < NGATES) {
        float th = angles[tid];
        s_cos[tid] = cosf(th);
        s_sin[tid] = sinf(th);
    }

    const float* src = in + (size_t)b * DD * DD + (size_t)r0 * DD;

    // ---------- load: interleave rows 4qr..4qr+3 into float4 lanes --------
    {
        #pragma unroll 5
        for (int k = 0; k < QFULL / THREADS; k++) {          // 10 uniform iters
            int n  = tid + k * THREADS;
            int qr = n / DD;
            int c  = n - qr * DD;
            const float* s0 = src + (size_t)(4 * qr) * DD + c;
            tileQ[qr * STRIDEQ + c] =
                make_float4(__ldg(s0), __ldg(s0 + DD),
                            __ldg(s0 + 2 * DD), __ldg(s0 + 3 * DD));
        }
        int n = tid + QFULL;                                 // tail: 340
        if (n < QITEMS) {
            int qr = n / DD;
            int c  = n - qr * DD;
            const float* s0 = src + (size_t)(4 * qr) * DD + c;
            tileQ[qr * STRIDEQ + c] =
                make_float4(__ldg(s0), __ldg(s0 + DD),
                            __ldg(s0 + 2 * DD), __ldg(s0 + 3 * DD));
        }
        // pair row (rows 28, 29)
        for (int c = tid; c < DD; c += THREADS)
            tileP[c] = f2pack(__ldg(src + (size_t)28 * DD + c),
                              __ldg(src + (size_t)29 * DD + c));
    }
    __syncthreads();

    // ---------- rotate: warp-autonomous, frontier-carry, table-free -------
    // Walk (proven R9/R10): off init = x-1; data step = (g < x-1) ? 38-g : 1;
    // update step = (g <= x-1) ? 38-g : 1; active iff g<x-1 or g>x;
    // fresh-load xi at g==0 or g==x+1; flush at g==x-2 or g==38.
    {
        const int w    = tid >> 5;
        const int lane = tid & 31;
        const int x0 = lane, x1 = 32 + lane;
        const bool a1 = (lane < 8);
        int off0 = x0 - 1, off1 = x1 - 1;

        if (w < NQR) {                                  // quad path, 4 rows
            float4* rp = tileQ + w * STRIDEQ;
            u64 c0l = 0, c0h = 0, c1l = 0, c1h = 0;     // carries (2 slots)
            #pragma unroll 1
            for (int g = 0; g < NGATES; g++) {
                const u64  c2  = f2pack(s_cos[g],  s_cos[g]);
                const u64  s2  = f2pack(s_sin[g],  s_sin[g]);
                const u64  ns2 = f2pack(-s_sin[g], -s_sin[g]);
                const int  bs  = 38 - g;
                const bool g0  = (g == 0), gLast = (g == NGATES - 1);

                #define DOITQ(X, OFF, CLO, CHI, ACT)  {                      \
                    const bool inB = (g < (X) - 1);                          \
                    if ((ACT) && (inB || g > (X))) {                         \
                        const int step = inB ? bs : 1;                       \
                        float4* pi = rp + (OFF);                             \
                        float4* pj = pi + step;                              \
                        float4 xj4 = *pj;                                    \
                        u64 xjl = f2pack(xj4.x, xj4.y);                      \
                        u64 xjh = f2pack(xj4.z, xj4.w);                      \
                        u64 xil, xih;                                        \
                        if (g0 || g == (X) + 1) {                            \
                            float4 xi4 = *pi;                                \
                            xil = f2pack(xi4.x, xi4.y);                      \
                            xih = f2pack(xi4.z, xi4.w);                      \
                        } else { xil = (CLO); xih = (CHI); }                 \
                        u64 nil = f2fma(c2, xil, f2mul(ns2, xjl));           \
                        u64 nih = f2fma(c2, xih, f2mul(ns2, xjh));           \
                        float4 o;                                            \
                        f2unpack(o.x, o.y, nil);                             \
                        f2unpack(o.z, o.w, nih);                             \
                        *pi = o;                                             \
                        u64 njl = f2fma(s2, xil, f2mul(c2, xjl));            \
                        u64 njh = f2fma(s2, xih, f2mul(c2, xjh));            \
                        (CLO) = njl; (CHI) = njh;                            \
                        if (g == (X) - 2 || gLast) {                         \
                            float4 oj;                                       \
                            f2unpack(oj.x, oj.y, njl);                       \
                            f2unpack(oj.z, oj.w, njh);                       \
                            *pj = oj;                                        \
                        }                                                    \
                    }                                                        \
                    (OFF) += (g <= (X) - 1) ? bs : 1; }

                DOITQ(x0, off0, c0l, c0h, true)
                DOITQ(x1, off1, c1l, c1h, a1)
                #undef DOITQ
                __syncwarp();
            }
        } else if (w == NQR) {                          // pair path, rows 28-29
            u64* rp = tileP;
            u64 carry0 = 0, carry1 = 0;
            #pragma unroll 1
            for (int g = 0; g < NGATES; g++) {
                const u64  c2  = f2pack(s_cos[g],  s_cos[g]);
                const u64  s2  = f2pack(s_sin[g],  s_sin[g]);
                const u64  ns2 = f2pack(-s_sin[g], -s_sin[g]);
                const int  bs  = 38 - g;
                const bool g0  = (g == 0), gLast = (g == NGATES - 1);

                #define DOITP(X, OFF, CARRY, ACT)  {                         \
                    const bool inB = (g < (X) - 1);                          \
                    if ((ACT) && (inB || g > (X))) {                         \
                        const int step = inB ? bs : 1;                       \
                        u64* pi = rp + (OFF);                                \
                        u64* pj = pi + step;                                 \
                        u64 xj = *pj;                                        \
                        u64 xi = (g0 || g == (X) + 1) ? *pi : (CARRY);       \
                        *pi = f2fma(c2, xi, f2mul(ns2, xj));                 \
                        u64 nj = f2fma(s2, xi, f2mul(c2, xj));               \
                        (CARRY) = nj;                                        \
                        if (g == (X) - 2 || gLast) *pj = nj;                 \
                    }                                                        \
                    (OFF) += (g <= (X) - 1) ? bs : 1; }

                DOITP(x0, off0, carry0, true)
                DOITP(x1, off1, carry1, a1)
                #undef DOITP
                __syncwarp();
            }
        }
    }
    __syncthreads();

    // ---------- transposed store: out[b, col, r0 + ...] -------------------
    {
        float* dstb = out + (size_t)b * DD * DD + r0;
        // quad rows: 2x STG.64 per item (r0 = 30t is 2 mod 4 -> no STG.128)
        #pragma unroll 4
        for (int n = tid; n < QITEMS; n += THREADS) {
            int col = n / NQR;
            int qr  = n - col * NQR;
            float4 v = tileQ[qr * STRIDEQ + col];            // LDS.128
            float* d = dstb + (size_t)col * DD + 4 * qr;
            *(float2*)(d)     = make_float2(v.x, v.y);       // STG.64
            *(float2*)(d + 2) = make_float2(v.z, v.w);       // STG.64
        }
        // pair row (rows 28, 29)
        for (int col = tid; col < DD; col += THREADS)
            *(u64*)(dstb + (size_t)col * DD + 28) = tileP[col];
    }
}

__global__ __launch_bounds__(THREADS, 2)
void rbs_pass1(const float* __restrict__ in, const float* __restrict__ angles) {
    rbs_body(in, g_tmp, angles);
}

__global__ __launch_bounds__(THREADS, 2)
void rbs_pass2(float* __restrict__ out, const float* __restrict__ angles) {
    rbs_body(g_tmp, out, angles);
}

extern "C" void kernel_launch(void* const* d_in, const int* in_sizes, int n_in,
                              void* d_out, int out_size) {
    const float* input_state = (const float*)d_in[0];  // [64,780,780] f32
    const float* angles      = (const float*)d_in[1];  // [39] f32
    float* out = (float*)d_out;

    const int smem = QBYTES + DD * sizeof(u64);        // 93,712 B dynamic
    cudaFuncSetAttribute(rbs_pass1, cudaFuncAttributeMaxDynamicSharedMemorySize, smem);
    cudaFuncSetAttribute(rbs_pass2, cudaFuncAttributeMaxDynamicSharedMemorySize, smem);

    dim3 grid(NBATCH * NTILES);   // 1664 blocks
    rbs_pass1<<<grid, THREADS, smem>>>(input_state, angles);
    rbs_pass2<<<grid, THREADS, smem>>>(out, angles);
}

// round 12
// speedup vs baseline: 1.1031x; 1.1031x over previous
#include <cuda_runtime.h>

// Dense_RBS_density_3D: rho_out = W rho W^T, W = 39 sparse Givens layers
// (38 disjoint 2x2 column rotations each) on the C(40,2)=780-dim basis.
// K(M) = (M W^T)^T = W M^T applied twice => W rho W^T. Two launches with a
// private __device__ scratch between.
//
// R12 = R10 kernel (float2 row-pairing, table-free offset walk, frontier
// carry, 15.. now 10 rotate warps) with 20-row tiles => 62.5 KB smem =>
// 3 CTAs/SM. Rotate warps/SM unchanged (3x10 = 2x15); occupancy 47->70%.
// R8's 3-CTA regression cause (per-block offset-table rebuild) is gone since
// R9 made the walk table-free.

#define DD      780
#define NGATES  39
#define NBATCH  64
#define RROWS   20            // rows per tile
#define NPR     10            // pair-rows (float2 lanes)
#define NTILES  39            // 780 / 20
#define STRIDE2 781           // float2 stride per pair-row (odd)
#define THREADS 512
#define NITEMS  (NPR * DD)                       // 7800 load/store items
#define NFULL   ((NITEMS / THREADS) * THREADS)   // 7680

__device__ float g_tmp[(size_t)NBATCH * DD * DD];  // 155.7 MB scratch

typedef unsigned long long u64;

__device__ __forceinline__ u64 f2pack(float lo, float hi) {
    u64 r; asm("mov.b64 %0, {%1, %2};" : "=l"(r) : "f"(lo), "f"(hi)); return r;
}
__device__ __forceinline__ u64 f2mul(u64 a, u64 b) {
    u64 r; asm("mul.rn.f32x2 %0, %1, %2;" : "=l"(r) : "l"(a), "l"(b)); return r;
}
__device__ __forceinline__ u64 f2fma(u64 a, u64 b, u64 c) {
    u64 r; asm("fma.rn.f32x2 %0, %1, %2, %3;" : "=l"(r) : "l"(a), "l"(b), "l"(c));
    return r;
}

__device__ __forceinline__ void rbs_body(const float* __restrict__ in,
                                         float* __restrict__ out,
                                         const float* __restrict__ angles) {
    extern __shared__ u64 tile2[];                  // NPR * STRIDE2 float2
    __shared__ float s_cos[NGATES], s_sin[NGATES];

    const int tid = threadIdx.x;
    const int b   = blockIdx.x / NTILES;
    const int t   = blockIdx.x - b * NTILES;
    const int r0  = t * RROWS;

    if (tid < NGATES) {
        float th = angles[tid];
        s_cos[tid] = cosf(th);
        s_sin[tid] = sinf(th);
    }

    // ---------- load: interleave rows 2pr, 2pr+1 into float2 lanes --------
    {
        const float* src = in + (size_t)b * DD * DD + (size_t)r0 * DD;
        #pragma unroll 3
        for (int k = 0; k < NFULL / THREADS; k++) {          // 15 uniform iters
            int n  = tid + k * THREADS;
            int pr = n / DD;
            int c  = n - pr * DD;
            float a0 = __ldg(src + (size_t)(2 * pr)     * DD + c);
            float a1 = __ldg(src + (size_t)(2 * pr + 1) * DD + c);
            tile2[pr * STRIDE2 + c] = f2pack(a0, a1);
        }
        int n = tid + NFULL;                                 // tail: 120 threads
        if (n < NITEMS) {
            int pr = n / DD;
            int c  = n - pr * DD;
            float a0 = __ldg(src + (size_t)(2 * pr)     * DD + c);
            float a1 = __ldg(src + (size_t)(2 * pr + 1) * DD + c);
            tile2[pr * STRIDE2 + c] = f2pack(a0, a1);
        }
    }
    __syncthreads();

    // ---------- rotate: warp-autonomous, frontier-carry, table-free -------
    // Walk (proven R9/R10): off init = x-1; data step = (g < x-1) ? 38-g : 1;
    // update step = (g <= x-1) ? 38-g : 1; active iff g<x-1 or g>x;
    // fresh-load xi at g==0 or g==x+1; flush carry at g==x-2 or g==38.
    {
        const int w    = tid >> 5;
        const int lane = tid & 31;
        if (w < NPR) {
            u64* rp = &tile2[w * STRIDE2];
            const int  x0 = lane,      x1 = 32 + lane;       // two item slots
            const bool a1 = (lane < 8);                      // x1 in [32,40)
            int off0 = x0 - 1, off1 = x1 - 1;
            u64 carry0 = 0, carry1 = 0;

            #pragma unroll 1
            for (int g = 0; g < NGATES; g++) {
                const u64  c2  = f2pack(s_cos[g],  s_cos[g]);
                const u64  s2  = f2pack(s_sin[g],  s_sin[g]);
                const u64  ns2 = f2pack(-s_sin[g], -s_sin[g]);
                const int  bs  = 38 - g;
                const bool g0  = (g == 0), gLast = (g == NGATES - 1);

                #define DOIT(X, OFF, CARRY, ACT)  {                        \
                    const bool inB = (g < (X) - 1);                        \
                    if ((ACT) && (inB || g > (X))) {                       \
                        const int step = inB ? bs : 1;                     \
                        u64* pi = rp + (OFF);                              \
                        u64* pj = pi + step;                               \
                        u64 xj = *pj;                                      \
                        u64 xi = (g0 || g == (X) + 1) ? *pi : (CARRY);     \
                        *pi = f2fma(c2, xi, f2mul(ns2, xj));               \
                        u64 nj = f2fma(s2, xi, f2mul(c2, xj));             \
                        (CARRY) = nj;                                      \
                        if (g == (X) - 2 || gLast) *pj = nj;               \
                    }                                                      \
                    (OFF) += (g <= (X) - 1) ? bs : 1; }

                DOIT(x0, off0, carry0, true)
                DOIT(x1, off1, carry1, a1)
                #undef DOIT
                __syncwarp();
            }
        }
    }
    __syncthreads();

    // ---------- transposed store: out[b, col, r0+2pr..+1], STG.64 ---------
    {
        float* dstb = out + (size_t)b * DD * DD + r0;
        #pragma unroll 2
        for (int n = tid; n < NITEMS; n += THREADS) {
            int col = n / NPR;
            int pr  = n - col * NPR;
            u64 v = tile2[pr * STRIDE2 + col];               // LDS.64
            *(u64*)(dstb + (size_t)col * DD + 2 * pr) = v;   // STG.64
        }
    }
}

__global__ __launch_bounds__(THREADS, 3)
void rbs_pass1(const float* __restrict__ in, const float* __restrict__ angles) {
    rbs_body(in, g_tmp, angles);
}

__global__ __launch_bounds__(THREADS, 3)
void rbs_pass2(float* __restrict__ out, const float* __restrict__ angles) {
    rbs_body(g_tmp, out, angles);
}

extern "C" void kernel_launch(void* const* d_in, const int* in_sizes, int n_in,
                              void* d_out, int out_size) {
    const float* input_state = (const float*)d_in[0];  // [64,780,780] f32
    const float* angles      = (const float*)d_in[1];  // [39] f32
    float* out = (float*)d_out;

    const int smem = NPR * STRIDE2 * sizeof(u64);      // 62,480 B dynamic
    cudaFuncSetAttribute(rbs_pass1, cudaFuncAttributeMaxDynamicSharedMemorySize, smem);
    cudaFuncSetAttribute(rbs_pass2, cudaFuncAttributeMaxDynamicSharedMemorySize, smem);

    dim3 grid(NBATCH * NTILES);   // 2496 blocks
    rbs_pass1<<<grid, THREADS, smem>>>(input_state, angles);
    rbs_pass2<<<grid, THREADS, smem>>>(out, angles);
}

// round 13
// speedup vs baseline: 1.1412x; 1.0345x over previous
#include <cuda_runtime.h>

// Dense_RBS_density_3D: rho_out = W rho W^T, W = 39 sparse Givens layers
// (38 disjoint 2x2 column rotations each) on the C(40,2)=780-dim basis.
// K(M) = (M W^T)^T = W M^T applied twice => W rho W^T. Two launches with a
// private __device__ scratch between.
//
// R13 = R10 (float2 row-pairing, table-free walk, frontier carry, 15 rotate
// warps, 30-row tiles, 2 CTAs/SM, 1664 blocks) with THREADS 512 -> 1024:
// occupancy 47% -> ~100% (64 warps/SM). Rotate phase byte-identical on warps
// 0-14; the extra warps accelerate the latency-exposed load/store phases.
// Geometry invariants from R8/R11/R12 postmortems: block count and tile shape
// unchanged; rotate warp count unchanged.

#define DD      780
#define NGATES  39
#define NBATCH  64
#define RROWS   30            // rows per tile
#define NPR     15            // pair-rows (float2 lanes)
#define NTILES  26            // 780 / 30
#define STRIDE2 781           // float2 stride per pair-row (odd)
#define THREADS 1024
#define NITEMS  (NPR * DD)                       // 11700 load/store items
#define NFULL   ((NITEMS / THREADS) * THREADS)   // 11264

__device__ float g_tmp[(size_t)NBATCH * DD * DD];  // 155.7 MB scratch

typedef unsigned long long u64;

__device__ __forceinline__ u64 f2pack(float lo, float hi) {
    u64 r; asm("mov.b64 %0, {%1, %2};" : "=l"(r) : "f"(lo), "f"(hi)); return r;
}
__device__ __forceinline__ u64 f2mul(u64 a, u64 b) {
    u64 r; asm("mul.rn.f32x2 %0, %1, %2;" : "=l"(r) : "l"(a), "l"(b)); return r;
}
__device__ __forceinline__ u64 f2fma(u64 a, u64 b, u64 c) {
    u64 r; asm("fma.rn.f32x2 %0, %1, %2, %3;" : "=l"(r) : "l"(a), "l"(b), "l"(c));
    return r;
}

__device__ __forceinline__ void rbs_body(const float* __restrict__ in,
                                         float* __restrict__ out,
                                         const float* __restrict__ angles) {
    extern __shared__ u64 tile2[];                  // NPR * STRIDE2 float2
    __shared__ float s_cos[NGATES], s_sin[NGATES];

    const int tid = threadIdx.x;
    const int b   = blockIdx.x / NTILES;
    const int t   = blockIdx.x - b * NTILES;
    const int r0  = t * RROWS;

    if (tid < NGATES) {
        float th = angles[tid];
        s_cos[tid] = cosf(th);
        s_sin[tid] = sinf(th);
    }

    // ---------- load: interleave rows 2pr, 2pr+1 into float2 lanes --------
    {
        const float* src = in + (size_t)b * DD * DD + (size_t)r0 * DD;
        #pragma unroll 11
        for (int k = 0; k < NFULL / THREADS; k++) {          // 11 uniform iters
            int n  = tid + k * THREADS;
            int pr = n / DD;
            int c  = n - pr * DD;
            float a0 = __ldg(src + (size_t)(2 * pr)     * DD + c);
            float a1 = __ldg(src + (size_t)(2 * pr + 1) * DD + c);
            tile2[pr * STRIDE2 + c] = f2pack(a0, a1);
        }
        int n = tid + NFULL;                                 // tail: 436 threads
        if (n < NITEMS) {
            int pr = n / DD;
            int c  = n - pr * DD;
            float a0 = __ldg(src + (size_t)(2 * pr)     * DD + c);
            float a1 = __ldg(src + (size_t)(2 * pr + 1) * DD + c);
            tile2[pr * STRIDE2 + c] = f2pack(a0, a1);
        }
    }
    __syncthreads();

    // ---------- rotate: warp-autonomous, frontier-carry, table-free -------
    // Walk (proven R9/R10): off init = x-1; data step = (g < x-1) ? 38-g : 1;
    // update step = (g <= x-1) ? 38-g : 1; active iff g<x-1 or g>x;
    // fresh-load xi at g==0 or g==x+1; flush carry at g==x-2 or g==38.
    {
        const int w    = tid >> 5;
        const int lane = tid & 31;
        if (w < NPR) {
            u64* rp = &tile2[w * STRIDE2];
            const int  x0 = lane,      x1 = 32 + lane;       // two item slots
            const bool a1 = (lane < 8);                      // x1 in [32,40)
            int off0 = x0 - 1, off1 = x1 - 1;
            u64 carry0 = 0, carry1 = 0;

            #pragma unroll 1
            for (int g = 0; g < NGATES; g++) {
                const u64  c2  = f2pack(s_cos[g],  s_cos[g]);
                const u64  s2  = f2pack(s_sin[g],  s_sin[g]);
                const u64  ns2 = f2pack(-s_sin[g], -s_sin[g]);
                const int  bs  = 38 - g;
                const bool g0  = (g == 0), gLast = (g == NGATES - 1);

                #define DOIT(X, OFF, CARRY, ACT)  {                        \
                    const bool inB = (g < (X) - 1);                        \
                    if ((ACT) && (inB || g > (X))) {                       \
                        const int step = inB ? bs : 1;                     \
                        u64* pi = rp + (OFF);                              \
                        u64* pj = pi + step;                               \
                        u64 xj = *pj;                                      \
                        u64 xi = (g0 || g == (X) + 1) ? *pi : (CARRY);     \
                        *pi = f2fma(c2, xi, f2mul(ns2, xj));               \
                        u64 nj = f2fma(s2, xi, f2mul(c2, xj));             \
                        (CARRY) = nj;                                      \
                        if (g == (X) - 2 || gLast) *pj = nj;               \
                    }                                                      \
                    (OFF) += (g <= (X) - 1) ? bs : 1; }

                DOIT(x0, off0, carry0, true)
                DOIT(x1, off1, carry1, a1)
                #undef DOIT
                __syncwarp();
            }
        }
    }
    __syncthreads();

    // ---------- transposed store: out[b, col, r0+2pr..+1], STG.64 ---------
    {
        float* dstb = out + (size_t)b * DD * DD + r0;
        #pragma unroll 4
        for (int n = tid; n < NITEMS; n += THREADS) {
            int col = n / NPR;
            int pr  = n - col * NPR;
            u64 v = tile2[pr * STRIDE2 + col];               // LDS.64
            *(u64*)(dstb + (size_t)col * DD + 2 * pr) = v;   // STG.64
        }
    }
}

__global__ __launch_bounds__(THREADS, 2)
void rbs_pass1(const float* __restrict__ in, const float* __restrict__ angles) {
    rbs_body(in, g_tmp, angles);
}

__global__ __launch_bounds__(THREADS, 2)
void rbs_pass2(float* __restrict__ out, const float* __restrict__ angles) {
    rbs_body(g_tmp, out, angles);
}

extern "C" void kernel_launch(void* const* d_in, const int* in_sizes, int n_in,
                              void* d_out, int out_size) {
    const float* input_state = (const float*)d_in[0];  // [64,780,780] f32
    const float* angles      = (const float*)d_in[1];  // [39] f32
    float* out = (float*)d_out;

    const int smem = NPR * STRIDE2 * sizeof(u64);      // 93,720 B dynamic
    cudaFuncSetAttribute(rbs_pass1, cudaFuncAttributeMaxDynamicSharedMemorySize, smem);
    cudaFuncSetAttribute(rbs_pass2, cudaFuncAttributeMaxDynamicSharedMemorySize, smem);

    dim3 grid(NBATCH * NTILES);   // 1664 blocks
    rbs_pass1<<<grid, THREADS, smem>>>(input_state, angles);
    rbs_pass2<<<grid, THREADS, smem>>>(out, angles);
}

// round 14
// speedup vs baseline: 1.2977x; 1.1371x over previous
#include <cuda_runtime.h>

// Dense_RBS_density_3D: rho_out = W rho W^T, W = 39 sparse Givens layers
// (38 disjoint 2x2 column rotations each) on the C(40,2)=780-dim basis.
// K(M) = (M W^T)^T = W M^T applied twice => W rho W^T. Two launches with a
// private __device__ scratch between.
//
// R14 = R10 (champion: float2 row-pairing, table-free walk, frontier carry,
// 15 rotate warps, 30-row tiles, 512 thr, 2 CTAs/SM, 1664 blocks) with the
// rotate loop FULLY UNROLLED (g compile-time: bs/g0/gLast/predicates fold to
// immediates, no loop branch) and PRE-PACKED u64 trig tables (3 broadcast
// LDS.64 per gate instead of 2 LDS.32 + negate + 3 packs). ~10 of ~30
// instr/gate/warp removed. Rotate structure/sync otherwise byte-identical.

#define DD      780
#define NGATES  39
#define NBATCH  64
#define RROWS   30            // rows per tile
#define NPR     15            // pair-rows (float2 lanes)
#define NTILES  26            // 780 / 30
#define STRIDE2 781           // float2 stride per pair-row (odd)
#define THREADS 512
#define NITEMS  (NPR * DD)                       // 11700 load/store items
#define NFULL   ((NITEMS / THREADS) * THREADS)   // 11264

__device__ float g_tmp[(size_t)NBATCH * DD * DD];  // 155.7 MB scratch

typedef unsigned long long u64;

__device__ __forceinline__ u64 f2pack(float lo, float hi) {
    u64 r; asm("mov.b64 %0, {%1, %2};" : "=l"(r) : "f"(lo), "f"(hi)); return r;
}
__device__ __forceinline__ u64 f2mul(u64 a, u64 b) {
    u64 r; asm("mul.rn.f32x2 %0, %1, %2;" : "=l"(r) : "l"(a), "l"(b)); return r;
}
__device__ __forceinline__ u64 f2fma(u64 a, u64 b, u64 c) {
    u64 r; asm("fma.rn.f32x2 %0, %1, %2, %3;" : "=l"(r) : "l"(a), "l"(b), "l"(c));
    return r;
}

__device__ __forceinline__ void rbs_body(const float* __restrict__ in,
                                         float* __restrict__ out,
                                         const float* __restrict__ angles) {
    extern __shared__ u64 tile2[];                  // NPR * STRIDE2 float2
    __shared__ u64 s_c2[NGATES], s_s2[NGATES], s_ns2[NGATES];

    const int tid = threadIdx.x;
    const int b   = blockIdx.x / NTILES;
    const int t   = blockIdx.x - b * NTILES;
    const int r0  = t * RROWS;

    if (tid < NGATES) {
        float th = angles[tid];
        float c = cosf(th), s = sinf(th);
        s_c2[tid]  = f2pack(c, c);
        s_s2[tid]  = f2pack(s, s);
        s_ns2[tid] = f2pack(-s, -s);
    }

    // ---------- load: interleave rows 2pr, 2pr+1 into float2 lanes --------
    {
        const float* src = in + (size_t)b * DD * DD + (size_t)r0 * DD;
        #pragma unroll 11
        for (int k = 0; k < NFULL / THREADS; k++) {          // 22 uniform iters
            int n  = tid + k * THREADS;
            int pr = n / DD;
            int c  = n - pr * DD;
            float a0 = __ldg(src + (size_t)(2 * pr)     * DD + c);
            float a1 = __ldg(src + (size_t)(2 * pr + 1) * DD + c);
            tile2[pr * STRIDE2 + c] = f2pack(a0, a1);
        }
        int n = tid + NFULL;                                 // tail: 436 threads
        if (n < NITEMS) {
            int pr = n / DD;
            int c  = n - pr * DD;
            float a0 = __ldg(src + (size_t)(2 * pr)     * DD + c);
            float a1 = __ldg(src + (size_t)(2 * pr + 1) * DD + c);
            tile2[pr * STRIDE2 + c] = f2pack(a0, a1);
        }
    }
    __syncthreads();

    // ---------- rotate: warp-autonomous, frontier-carry, table-free -------
    // Walk (proven R9/R10): off init = x-1; data step = (g < x-1) ? 38-g : 1;
    // update step = (g <= x-1) ? 38-g : 1; active iff g<x-1 or g>x;
    // fresh-load xi at g==0 or g==x+1; flush carry at g==x-2 or g==38.
    // FULLY UNROLLED: g is compile-time in every predicate and step.
    {
        const int w    = tid >> 5;
        const int lane = tid & 31;
        if (w < NPR) {
            u64* rp = &tile2[w * STRIDE2];
            const int  x0 = lane,      x1 = 32 + lane;       // two item slots
            const bool a1 = (lane < 8);                      // x1 in [32,40)
            int off0 = x0 - 1, off1 = x1 - 1;
            u64 carry0 = 0, carry1 = 0;

            #pragma unroll
            for (int g = 0; g < NGATES; g++) {
                const u64 c2  = s_c2[g];
                const u64 s2  = s_s2[g];
                const u64 ns2 = s_ns2[g];
                const int bs  = 38 - g;                      // compile-time
                const bool g0 = (g == 0), gLast = (g == NGATES - 1);

                #define DOIT(X, OFF, CARRY, ACT)  {                        \
                    const bool inB = (g < (X) - 1);                        \
                    if ((ACT) && (inB || g > (X))) {                       \
                        const int step = inB ? bs : 1;                     \
                        u64* pi = rp + (OFF);                              \
                        u64* pj = pi + step;                               \
                        u64 xj = *pj;                                      \
                        u64 xi = (g0 || g == (X) + 1) ? *pi : (CARRY);     \
                        *pi = f2fma(c2, xi, f2mul(ns2, xj));               \
                        u64 nj = f2fma(s2, xi, f2mul(c2, xj));             \
                        (CARRY) = nj;                                      \
                        if (g == (X) - 2 || gLast) *pj = nj;               \
                    }                                                      \
                    (OFF) += (g <= (X) - 1) ? bs : 1; }

                DOIT(x0, off0, carry0, true)
                DOIT(x1, off1, carry1, a1)
                #undef DOIT
                __syncwarp();
            }
        }
    }
    __syncthreads();

    // ---------- transposed store: out[b, col, r0+2pr..+1], STG.64 ---------
    {
        float* dstb = out + (size_t)b * DD * DD + r0;
        #pragma unroll 4
        for (int n = tid; n < NITEMS; n += THREADS) {
            int col = n / NPR;
            int pr  = n - col * NPR;
            u64 v = tile2[pr * STRIDE2 + col];               // LDS.64
            *(u64*)(dstb + (size_t)col * DD + 2 * pr) = v;   // STG.64
        }
    }
}

__global__ __launch_bounds__(THREADS, 2)
void rbs_pass1(const float* __restrict__ in, const float* __restrict__ angles) {
    rbs_body(in, g_tmp, angles);
}

__global__ __launch_bounds__(THREADS, 2)
void rbs_pass2(float* __restrict__ out, const float* __restrict__ angles) {
    rbs_body(g_tmp, out, angles);
}

extern "C" void kernel_launch(void* const* d_in, const int* in_sizes, int n_in,
                              void* d_out, int out_size) {
    const float* input_state = (const float*)d_in[0];  // [64,780,780] f32
    const float* angles      = (const float*)d_in[1];  // [39] f32
    float* out = (float*)d_out;

    const int smem = NPR * STRIDE2 * sizeof(u64);      // 93,720 B dynamic
    cudaFuncSetAttribute(rbs_pass1, cudaFuncAttributeMaxDynamicSharedMemorySize, smem);
    cudaFuncSetAttribute(rbs_pass2, cudaFuncAttributeMaxDynamicSharedMemorySize, smem);

    dim3 grid(NBATCH * NTILES);   // 1664 blocks
    rbs_pass1<<<grid, THREADS, smem>>>(input_state, angles);
    rbs_pass2<<<grid, THREADS, smem>>>(out, angles);
}

// round 15
// speedup vs baseline: 1.3666x; 1.0531x over previous
#include <cuda_runtime.h>

// Dense_RBS_density_3D: rho_out = W rho W^T, W = 39 sparse Givens layers
// (38 disjoint 2x2 column rotations each) on the C(40,2)=780-dim basis.
// K(M) = (M W^T)^T = W M^T applied twice => W rho W^T. Two launches with a
// private __device__ scratch between.
//
// R15 vs R14 (champion; same geometry: float2 row-pairing, table-free walk,
// frontier carry, 15 rotate warps, 30-row tiles, 512 thr, 2 CTAs/SM):
//  (1) ONE packed trig broadcast per gate (s_cs=(c,s); c2/s2 via packs,
//      ns2 via XOR sign flip) instead of 3 LDS.64 -> ~1170 fewer smem
//      wavefronts/block.
//  (2) warp-local load: rotate warp w loads its own rows 2w,2w+1 and enters
//      the gate loop after a __syncwarp — the block-wide load barrier is gone
//      (only a trivial post-trig barrier + the pre-store barrier remain).

#define DD      780
#define NGATES  39
#define NBATCH  64
#define RROWS   30            // rows per tile
#define NPR     15            // pair-rows (float2 lanes)
#define NTILES  26            // 780 / 30
#define STRIDE2 781           // float2 stride per pair-row (odd)
#define THREADS 512
#define NITEMS  (NPR * DD)    // 11700 store items

__device__ float g_tmp[(size_t)NBATCH * DD * DD];  // 155.7 MB scratch

typedef unsigned long long u64;

__device__ __forceinline__ u64 f2pack(float lo, float hi) {
    u64 r; asm("mov.b64 %0, {%1, %2};" : "=l"(r) : "f"(lo), "f"(hi)); return r;
}
__device__ __forceinline__ void f2unpack(float& lo, float& hi, u64 v) {
    asm("mov.b64 {%0, %1}, %2;" : "=f"(lo), "=f"(hi) : "l"(v));
}
__device__ __forceinline__ u64 f2mul(u64 a, u64 b) {
    u64 r; asm("mul.rn.f32x2 %0, %1, %2;" : "=l"(r) : "l"(a), "l"(b)); return r;
}
__device__ __forceinline__ u64 f2fma(u64 a, u64 b, u64 c) {
    u64 r; asm("fma.rn.f32x2 %0, %1, %2, %3;" : "=l"(r) : "l"(a), "l"(b), "l"(c));
    return r;
}

__device__ __forceinline__ void rbs_body(const float* __restrict__ in,
                                         float* __restrict__ out,
                                         const float* __restrict__ angles) {
    extern __shared__ u64 tile2[];                  // NPR * STRIDE2 float2
    __shared__ u64 s_cs[NGATES];                    // packed (cos, sin)

    const int tid  = threadIdx.x;
    const int w    = tid >> 5;
    const int lane = tid & 31;
    const int b    = blockIdx.x / NTILES;
    const int t    = blockIdx.x - b * NTILES;
    const int r0   = t * RROWS;

    if (tid < NGATES) {
        float th = angles[tid];
        s_cs[tid] = f2pack(cosf(th), sinf(th));
    }
    __syncthreads();                                // trivial skew: trig only

    const float* src = in + (size_t)b * DD * DD + (size_t)r0 * DD;

    if (w < NPR) {
        // ---------- warp-local load: rows 2w, 2w+1 -> own tile region ------
        {
            const float* p0 = src + (size_t)(2 * w) * DD;
            const float* p1 = p0 + DD;
            u64* dst = &tile2[w * STRIDE2];
            #pragma unroll 8
            for (int k = 0; k < 24; k++) {                   // 24*32 = 768
                int c = (k << 5) + lane;
                dst[c] = f2pack(__ldg(p0 + c), __ldg(p1 + c));
            }
            int c = 768 + lane;                              // tail: 12 lanes
            if (c < DD)
                dst[c] = f2pack(__ldg(p0 + c), __ldg(p1 + c));
        }
        __syncwarp();                               // cross-lane smem visibility

        // ---------- rotate: warp-autonomous, frontier-carry, table-free ----
        // Walk (proven R9/R10): off init = x-1; data step = (g<x-1)?38-g:1;
        // update step = (g<=x-1)?38-g:1; active iff g<x-1 or g>x; fresh-load
        // xi at g==0 or g==x+1; flush carry at g==x-2 or g==38. FULLY UNROLLED.
        {
            u64* rp = &tile2[w * STRIDE2];
            const int  x0 = lane,      x1 = 32 + lane;       // two item slots
            const bool a1 = (lane < 8);                      // x1 in [32,40)
            int off0 = x0 - 1, off1 = x1 - 1;
            u64 carry0 = 0, carry1 = 0;

            #pragma unroll
            for (int g = 0; g < NGATES; g++) {
                u64 cs = s_cs[g];                            // 1 broadcast LDS
                float cf, sf; f2unpack(cf, sf, cs);
                const u64 c2  = f2pack(cf, cf);
                const u64 s2  = f2pack(sf, sf);
                const u64 ns2 = s2 ^ 0x8000000080000000ULL;  // sign flip
                const int bs  = 38 - g;                      // compile-time
                const bool g0 = (g == 0), gLast = (g == NGATES - 1);

                #define DOIT(X, OFF, CARRY, ACT)  {                        \
                    const bool inB = (g < (X) - 1);                        \
                    if ((ACT) && (inB || g > (X))) {                       \
                        const int step = inB ? bs : 1;                     \
                        u64* pi = rp + (OFF);                              \
                        u64* pj = pi + step;                               \
                        u64 xj = *pj;                                      \
                        u64 xi = (g0 || g == (X) + 1) ? *pi : (CARRY);     \
                        *pi = f2fma(c2, xi, f2mul(ns2, xj));               \
                        u64 nj = f2fma(s2, xi, f2mul(c2, xj));             \
                        (CARRY) = nj;                                      \
                        if (g == (X) - 2 || gLast) *pj = nj;               \
                    }                                                      \
                    (OFF) += (g <= (X) - 1) ? bs : 1; }

                DOIT(x0, off0, carry0, true)
                DOIT(x1, off1, carry1, a1)
                #undef DOIT
                __syncwarp();
            }
        }
    }
    __syncthreads();                                // all rows final

    // ---------- transposed store: out[b, col, r0+2pr..+1], STG.64 ---------
    {
        float* dstb = out + (size_t)b * DD * DD + r0;
        #pragma unroll 4
        for (int n = tid; n < NITEMS; n += THREADS) {
            int col = n / NPR;
            int pr  = n - col * NPR;
            u64 v = tile2[pr * STRIDE2 + col];               // LDS.64
            *(u64*)(dstb + (size_t)col * DD + 2 * pr) = v;   // STG.64
        }
    }
}

__global__ __launch_bounds__(THREADS, 2)
void rbs_pass1(const float* __restrict__ in, const float* __restrict__ angles) {
    rbs_body(in, g_tmp, angles);
}

__global__ __launch_bounds__(THREADS, 2)
void rbs_pass2(float* __restrict__ out, const float* __restrict__ angles) {
    rbs_body(g_tmp, out, angles);
}

extern "C" void kernel_launch(void* const* d_in, const int* in_sizes, int n_in,
                              void* d_out, int out_size) {
    const float* input_state = (const float*)d_in[0];  // [64,780,780] f32
    const float* angles      = (const float*)d_in[1];  // [39] f32
    float* out = (float*)d_out;

    const int smem = NPR * STRIDE2 * sizeof(u64);      // 93,720 B dynamic
    cudaFuncSetAttribute(rbs_pass1, cudaFuncAttributeMaxDynamicSharedMemorySize, smem);
    cudaFuncSetAttribute(rbs_pass2, cudaFuncAttributeMaxDynamicSharedMemorySize, smem);

    dim3 grid(NBATCH * NTILES);   // 1664 blocks
    rbs_pass1<<<grid, THREADS, smem>>>(input_state, angles);
    rbs_pass2<<<grid, THREADS, smem>>>(out, angles);
}